// round 8
// baseline (speedup 1.0000x reference)
#include <cuda_runtime.h>
#include <cuda_bf16.h>
#include <math.h>
#include <float.h>

#define WAY 5
#define SHOT 5
#define QUERY 15
#define EMB 640
#define NMEM 100000
#define NSIM (SHOT + NMEM)   // 100005 candidates per way
#define TOPK 8
#define EPS 1e-12f
#define INV_TEMP (1.0f / 64.0f)

#define ROWS 4               // rows per warp in k2
#define SPLITS 8             // scan splits per way in k3
#define CHUNK ((NSIM + SPLITS - 1) / SPLITS)   // 12501
#define NBLK (WAY * SPLITS)  // 40

typedef unsigned long long ull;

// ---------------- device scratch (static, allocation-free) ----------------
__device__ __align__(16) float g_c[WAY][EMB];   // per-way centroids
__device__ float g_supn[SHOT * WAY][EMB];       // normalized support rows
__device__ float g_sim[WAY][NSIM];              // similarity vector per way
__device__ float g_pv[WAY][SPLITS][TOPK];       // partial top-k values
__device__ int   g_pi[WAY][SPLITS][TOPK];       // partial top-k indices
__device__ unsigned g_done;                     // completion counter (self-resetting)

// ---------------- asm helpers ----------------------------------------------
__device__ __forceinline__ void ffma2(ull& d, ull a, ull b) {
    asm("fma.rn.f32x2 %0, %1, %2, %0;" : "+l"(d) : "l"(a), "l"(b));
}
__device__ __forceinline__ void ldg_nc_v2u64(ull& a, ull& b, const void* p) {
    asm("ld.global.nc.v2.u64 {%0,%1}, [%2];" : "=l"(a), "=l"(b) : "l"(p));
}
__device__ __forceinline__ float warp_sum(float v) {
#pragma unroll
    for (int o = 16; o; o >>= 1) v += __shfl_xor_sync(0xffffffffu, v, o);
    return v;
}
__device__ __forceinline__ float acc_fold(ull a) {
    return __uint_as_float((unsigned)a) + __uint_as_float((unsigned)(a >> 32));
}

// ---------------- kernel 1: supports -> sup_n, centroids, sim_sup ----------
__global__ void k1_support(const float* __restrict__ inst) {
    int wid  = threadIdx.x >> 5;
    int lane = threadIdx.x & 31;

    if (wid < SHOT * WAY) {
        const float* row = inst + wid * EMB;
        float v[20];
        float ss = 0.f;
#pragma unroll
        for (int i = 0; i < 20; i++) {
            v[i] = row[lane + 32 * i];
            ss += v[i] * v[i];
        }
        ss = warp_sum(ss);
        float inv = 1.0f / fmaxf(sqrtf(ss), EPS);
#pragma unroll
        for (int i = 0; i < 20; i++) g_supn[wid][lane + 32 * i] = v[i] * inv;
    }
    __syncthreads();

    for (int idx = threadIdx.x; idx < WAY * EMB; idx += blockDim.x) {
        int w = idx / EMB, d = idx % EMB;
        float s = 0.f;
#pragma unroll
        for (int t = 0; t < SHOT; t++) s += g_supn[t * WAY + w][d];
        g_c[w][d] = s * (1.0f / SHOT);
    }
    __syncthreads();

    if (wid < WAY * SHOT) {
        int w = wid / SHOT, t = wid % SHOT;
        float dot = 0.f;
        for (int i = lane; i < EMB; i += 32)
            dot += g_c[w][i] * g_supn[t * WAY + w][i];
        dot = warp_sum(dot);
        if (lane == 0) g_sim[w][t] = dot;
    }
}

// ---------------- kernel 2: memory-bank scan (FFMA2, target: DRAM-bound) ---
// Per chunk per row: 12 FFMA2 instead of 24 FFMA -> FMA pipe no longer binds.
// ~100 regs, 2 blocks/SM, 4 batched LDG.128 per warp per chunk.
__global__ void __launch_bounds__(256, 2) k2_memscan(const float* __restrict__ mem) {
    __shared__ ulonglong2 sc[WAY][EMB / 4];   // centroids as 2x f32x2, 12.8 KB
    {
        const ulonglong2* gc = (const ulonglong2*)g_c;
        ulonglong2* s = &sc[0][0];
        for (int i = threadIdx.x; i < WAY * EMB / 4; i += blockDim.x) s[i] = gc[i];
    }
    __syncthreads();

    int wg   = (blockIdx.x * blockDim.x + threadIdx.x) >> 5;
    int lane = threadIdx.x & 31;
    int row0 = wg * ROWS;
    if (row0 >= NMEM) return;

    const char* base = (const char*)(mem + (size_t)row0 * EMB);  // row = 2560 B

    ull acc[ROWS][6];
#pragma unroll
    for (int r = 0; r < ROWS; r++)
#pragma unroll
        for (int k = 0; k < 6; k++) acc[r][k] = 0ull;

#pragma unroll
    for (int i = 0; i < 5; i++) {
        int ci = lane + 32 * i;

        // batched independent 16B loads (4 in flight per warp)
        ull vx[ROWS], vy[ROWS];
#pragma unroll
        for (int r = 0; r < ROWS; r++)
            ldg_nc_v2u64(vx[r], vy[r], base + r * 2560 + ci * 16);

        ulonglong2 cw[WAY];
#pragma unroll
        for (int w = 0; w < WAY; w++) cw[w] = sc[w][ci];

#pragma unroll
        for (int r = 0; r < ROWS; r++) {
            ffma2(acc[r][5], vx[r], vx[r]);
            ffma2(acc[r][5], vy[r], vy[r]);
#pragma unroll
            for (int w = 0; w < WAY; w++) {
                ffma2(acc[r][w], vx[r], cw[w].x);
                ffma2(acc[r][w], vy[r], cw[w].y);
            }
        }
    }

#pragma unroll
    for (int r = 0; r < ROWS; r++) {
        float s0 = warp_sum(acc_fold(acc[r][0]));
        float s1 = warp_sum(acc_fold(acc[r][1]));
        float s2 = warp_sum(acc_fold(acc[r][2]));
        float s3 = warp_sum(acc_fold(acc[r][3]));
        float s4 = warp_sum(acc_fold(acc[r][4]));
        float s5 = warp_sum(acc_fold(acc[r][5]));
        float inv = 1.0f / fmaxf(sqrtf(s5), EPS);
        if (lane < WAY) {
            float a = (lane == 0) ? s0 :
                      (lane == 1) ? s1 :
                      (lane == 2) ? s2 :
                      (lane == 3) ? s3 : s4;
            g_sim[lane][SHOT + row0 + r] = a * inv;
        }
    }
}

// ---------------- top-k helpers ---------------------------------------------
__device__ __forceinline__ void merge8(float* av, int* ai,
                                       const float* bv, const int* bi) {
    float tv[TOPK]; int ti[TOPK];
    int ia = 0, ib = 0;
#pragma unroll
    for (int k = 0; k < TOPK; k++) {
        float va = av[ia], vb = bv[ib];
        bool takeA = (va > vb) || (va == vb && ai[ia] <= bi[ib]);
        if (takeA) { tv[k] = va; ti[k] = ai[ia]; ia++; }
        else       { tv[k] = vb; ti[k] = bi[ib]; ib++; }
    }
#pragma unroll
    for (int k = 0; k < TOPK; k++) { av[k] = tv[k]; ai[k] = ti[k]; }
}

__device__ __forceinline__ void insert8(float* bv, int* bi, float v, int i) {
    if (v > bv[TOPK - 1]) {
        int j = TOPK - 1;
        while (j > 0 && v > bv[j - 1]) { bv[j] = bv[j - 1]; bi[j] = bi[j - 1]; j--; }
        bv[j] = v; bi[j] = i;
    }
}

// tie-breaking insert (prefers smaller index on equal value)
__device__ __forceinline__ void insert8_tie(float* bv, int* bi, float v, int ix) {
    if (v > bv[TOPK - 1] || (v == bv[TOPK - 1] && ix < bi[TOPK - 1])) {
        int p = TOPK - 1;
        while (p > 0 && (v > bv[p - 1] || (v == bv[p - 1] && ix < bi[p - 1]))) {
            bv[p] = bv[p - 1]; bi[p] = bi[p - 1]; p--;
        }
        bv[p] = v; bi[p] = ix;
    }
}

// ---------------- kernel 3: partial top-8 + fused merge/proto/logits -------
#define K3_THREADS 256
__global__ void k3_fused(const float* __restrict__ inst,
                         const float* __restrict__ mem,
                         float* __restrict__ out) {
    int w = blockIdx.x / SPLITS;
    int s = blockIdx.x % SPLITS;
    int lo = s * CHUNK;
    int hi = min(lo + CHUNK, NSIM);
    const float* sim = g_sim[w];
    int tid = threadIdx.x;

    float bv[TOPK]; int bi[TOPK];
#pragma unroll
    for (int j = 0; j < TOPK; j++) { bv[j] = -FLT_MAX; bi[j] = 0x7fffffff; }

    int i = lo + tid;
    for (; i + 3 * K3_THREADS < hi; i += 4 * K3_THREADS) {
        float v0 = sim[i];
        float v1 = sim[i + K3_THREADS];
        float v2 = sim[i + 2 * K3_THREADS];
        float v3 = sim[i + 3 * K3_THREADS];
        insert8(bv, bi, v0, i);
        insert8(bv, bi, v1, i + K3_THREADS);
        insert8(bv, bi, v2, i + 2 * K3_THREADS);
        insert8(bv, bi, v3, i + 3 * K3_THREADS);
    }
    for (; i < hi; i += K3_THREADS) insert8(bv, bi, sim[i], i);

    __shared__ float shv[K3_THREADS][TOPK];
    __shared__ int   shi[K3_THREADS][TOPK];
#pragma unroll
    for (int j = 0; j < TOPK; j++) { shv[tid][j] = bv[j]; shi[tid][j] = bi[j]; }
    __syncthreads();

    for (int step = K3_THREADS / 2; step >= 1; step >>= 1) {
        if (tid < step)
            merge8(shv[tid], shi[tid], shv[tid + step], shi[tid + step]);
        __syncthreads();
    }
    if (tid < TOPK) {
        g_pv[w][s][tid] = shv[0][tid];
        g_pi[w][s][tid] = shi[0][tid];
    }
    // publish partials device-wide, then count completion
    __threadfence();
    __syncthreads();
    __shared__ unsigned slast;
    if (tid == 0) slast = atomicAdd(&g_done, 1u);
    __syncthreads();
    if (slast != NBLK - 1) return;

    // =============== LAST BLOCK: merge + proto + logits =====================
    if (tid == 0) g_done = 0;          // reset for next graph replay
    __threadfence();

    __shared__ float cv[WAY * SPLITS * TOPK];   // 320
    __shared__ int   cx[WAY * SPLITS * TOPK];
    for (int t = tid; t < WAY * SPLITS * TOPK; t += K3_THREADS) {
        cv[t] = (&g_pv[0][0][0])[t];
        cx[t] = (&g_pi[0][0][0])[t];
    }
    __syncthreads();

    __shared__ float fv[WAY][TOPK];
    __shared__ int   fi[WAY][TOPK];
    if (tid < WAY) {
        float mv[TOPK]; int mi[TOPK];
#pragma unroll
        for (int j = 0; j < TOPK; j++) { mv[j] = -FLT_MAX; mi[j] = 0x7fffffff; }
        for (int c = 0; c < SPLITS * TOPK; c++)
            insert8_tie(mv, mi, cv[tid * SPLITS * TOPK + c], cx[tid * SPLITS * TOPK + c]);
#pragma unroll
        for (int j = 0; j < TOPK; j++) { fv[tid][j] = mv[j]; fi[tid][j] = mi[j]; }
    }
    __syncthreads();

    // unnormalized prototypes (the /denom cancels under L2 normalization)
    __shared__ float sp[WAY][EMB];    // 12.8 KB
    for (int it = tid; it < WAY * EMB; it += K3_THREADS) {
        int w2 = it / EMB, d = it % EMB;
        float numer = 0.f;
#pragma unroll
        for (int j = 0; j < TOPK; j++) {
            int idx = fi[w2][j];
            const float* src = (idx < SHOT)
                ? inst + (size_t)(idx * WAY + w2) * EMB
                : mem + (size_t)(idx - SHOT) * EMB;
            numer += fv[w2][j] * src[d];
        }
        sp[w2][d] = numer;
    }
    __syncthreads();

    // deterministic per-way norm
    __shared__ float sred[8];
    __shared__ float sinv[WAY];
    int lane = tid & 31, wrp = tid >> 5;
    for (int w2 = 0; w2 < WAY; w2++) {
        float part = 0.f;
        for (int d = tid; d < EMB; d += K3_THREADS) {
            float p = sp[w2][d];
            part += p * p;
        }
        part = warp_sum(part);
        if (lane == 0) sred[wrp] = part;
        __syncthreads();
        if (tid == 0) {
            float t = 0.f;
#pragma unroll
            for (int u = 0; u < 8; u++) t += sred[u];
            sinv[w2] = INV_TEMP / fmaxf(sqrtf(t), EPS);
        }
        __syncthreads();
    }

    // logits: warp per query, 5 dots against smem prototypes
    for (int q = wrp; q < QUERY * WAY; q += 8) {
        const float* qr = inst + (size_t)(SHOT * WAY + q) * EMB;
        float qv[20];
#pragma unroll
        for (int u = 0; u < 20; u++) qv[u] = qr[lane + 32 * u];
#pragma unroll
        for (int w2 = 0; w2 < WAY; w2++) {
            float dot = 0.f;
#pragma unroll
            for (int u = 0; u < 20; u++) dot += qv[u] * sp[w2][lane + 32 * u];
            dot = warp_sum(dot);
            if (lane == 0) out[q * WAY + w2] = dot * sinv[w2];
        }
    }
}

// ---------------- launch ----------------------------------------------------
extern "C" void kernel_launch(void* const* d_in, const int* in_sizes, int n_in,
                              void* d_out, int out_size) {
    const float* inst = (const float*)d_in[0];   // [100, 640] fp32
    const float* mem  = (const float*)d_in[1];   // [100000, 640] fp32
    float* out = (float*)d_out;                  // [75, 5] fp32

    k1_support<<<1, 800>>>(inst);

    int warps  = (NMEM + ROWS - 1) / ROWS;       // 25000
    int blocks = (warps + 7) / 8;                // 3125
    k2_memscan<<<blocks, 256>>>(mem);

    k3_fused<<<NBLK, K3_THREADS>>>(inst, mem, out);
}